// round 11
// baseline (speedup 1.0000x reference)
#include <cuda_runtime.h>
#include <cstdint>

#define H        256
#define FOURH    1024
#define NG       2048
#define APG      64
#define GRID     296          // 2 CTAs/SM, all co-resident
#define TILE_F   (APG*H)
#define TILE_B   (TILE_F*4)   // 65536 bytes

// ---------------- device globals ----------------
__device__ float g_Wc[FOURH * H];      // (W_ih+W_hh)[n][k], row-major
__device__ float g_bc[FOURH];
__device__ float g_q0[H];
__device__ float g_c0[H];
__device__ float g_c [NG * H];
__device__ float g_h [NG * H];
__device__ float g_gates[NG * FOURH];
__device__ int   g_flagR[2][16];       // attn(s) r-complete per 128-graph block
__device__ int   g_flagG[2][16];       // gemm(s) tiles-complete per 128-row block

__device__ __forceinline__ float sigmoidf_(float v) {
    return 1.0f / (1.0f + __expf(-v));
}

// ---------------- prep: fold weights, step-0 state, zero flags ----------------
__global__ void prep_kernel(const float* __restrict__ W_ih,
                            const float* __restrict__ W_hh,
                            const float* __restrict__ b_ih,
                            const float* __restrict__ b_hh) {
    int idx = blockIdx.x * 256 + threadIdx.x;
    if (idx < FOURH * H) g_Wc[idx] = W_ih[idx] + W_hh[idx];
    if (idx < FOURH)     g_bc[idx] = b_ih[idx] + b_hh[idx];
    if (idx < H) {
        float gi = b_ih[idx]       + b_hh[idx];
        float gg = b_ih[512 + idx] + b_hh[512 + idx];
        float go = b_ih[768 + idx] + b_hh[768 + idx];
        float c  = sigmoidf_(gi) * tanhf(gg);
        g_c0[idx] = c;
        g_q0[idx] = sigmoidf_(go) * tanhf(c);
    }
    if (idx < 16) { g_flagR[0][idx] = 0; g_flagR[1][idx] = 0;
                    g_flagG[0][idx] = 0; g_flagG[1][idx] = 0; }
}

// ---------------- packed f32x2 helpers ----------------
__device__ __forceinline__ unsigned long long pack2(float lo, float hi) {
    unsigned long long r;
    asm("mov.b64 %0, {%1, %2};" : "=l"(r) : "f"(lo), "f"(hi));
    return r;
}
__device__ __forceinline__ void ffma2(unsigned long long& d,
                                      unsigned long long a,
                                      unsigned long long b) {
    asm("fma.rn.f32x2 %0, %1, %2, %0;" : "+l"(d) : "l"(a), "l"(b));
}
__device__ __forceinline__ float2 unpack2(unsigned long long v) {
    union { unsigned long long u; float2 f; } cv; cv.u = v; return cv.f;
}

__device__ __forceinline__ void poll_eq(volatile int* p, int target) {
    while (*p != target) __nanosleep(40);
}

// ---------------- SMEM layout (floats) ----------------
// xs[16384] | qs[256] | sc[64] | red[512] | Bs[64][136]
#define BS_STRIDE 136
#define SM_FLOATS (16384 + 256 + 64 + 512 + 64*BS_STRIDE)
#define SM_BYTES  (SM_FLOATS * 4 + 8)

__global__ void __launch_bounds__(512, 2)
fused_kernel(const float* __restrict__ x, float* __restrict__ out) {
    extern __shared__ __align__(16) unsigned char smraw[];
    float* xs  = (float*)smraw;              // [64][256]
    float* qs  = xs + TILE_F;                // [256]
    float* sc  = qs + H;                     // [64]
    float* red = sc + APG;                   // [512]
    float* Bs  = red + 512;                  // [64][136]

    uint32_t smem_base;
    asm("{ .reg .u64 t; cvta.to.shared.u64 t, %1; cvt.u32.u64 %0, t; }"
        : "=r"(smem_base) : "l"(smraw));
    uint32_t mbar = smem_base + SM_FLOATS * 4;

    int tid  = threadIdx.x;
    int lane = tid & 31;
    int w    = tid >> 5;
    int bid  = blockIdx.x;
    int G    = (NG - bid + GRID - 1) / GRID;   // 6 or 7
    int total = 3 * G;

    if (tid == 0)
        asm volatile("mbarrier.init.shared.b64 [%0], 1;" :: "r"(mbar) : "memory");
    __syncthreads();

    auto issue = [&](int j) {
        if (j < total && tid == 0) {
            int i2 = j % G;
            size_t g = (size_t)bid + (size_t)GRID * i2;
            asm volatile("mbarrier.arrive.expect_tx.shared.b64 _, [%0], %1;"
                         :: "r"(mbar), "r"(TILE_B) : "memory");
            asm volatile("cp.async.bulk.shared::cta.global.mbarrier::complete_tx::bytes "
                         "[%0], [%1], %2, [%3];"
                         :: "r"(smem_base), "l"(x + g * TILE_F), "r"(TILE_B), "r"(mbar)
                         : "memory");
        }
    };
    issue(0);

    int ph = 0;
    int jj = 0;
    for (int s = 0; s < 3; ++s) {
        // ================= attention pass s =================
        for (int ii = 0; ii < G; ++ii, ++jj) {
            int b = bid + GRID * ii;

            // wait for gates of this graph (produced by gemm phase s-1)
            if (s > 0) {
                if (tid == 0) {
                    poll_eq(&g_flagG[s - 1][b >> 7], 16);
                    __threadfence();
                }
                __syncthreads();
            }

            // fused LSTM pointwise -> q (overlaps in-flight TMA)
            if (tid < H) {
                int j = tid;
                float q;
                if (s == 0) {
                    q = g_q0[j];
                } else {
                    const float* gr = g_gates + (size_t)b * FOURH;
                    float gi = gr[j]       + g_bc[j];
                    float gf = gr[256 + j] + g_bc[256 + j];
                    float gg = gr[512 + j] + g_bc[512 + j];
                    float go = gr[768 + j] + g_bc[768 + j];
                    float cp = (s == 1) ? g_c0[j] : g_c[(size_t)b * H + j];
                    float c  = sigmoidf_(gf) * cp + sigmoidf_(gi) * tanhf(gg);
                    q = sigmoidf_(go) * tanhf(c);
                    if (s == 1) g_c[(size_t)b * H + j] = c;
                    if (s == 2) out[(size_t)b * (2 * H) + j] = q;
                }
                qs[j] = q;
            }

            // wait tile
            {
                uint32_t done;
                do {
                    asm volatile(
                        "{ .reg .pred p; "
                        "mbarrier.try_wait.parity.acquire.cta.shared::cta.b64 p, [%1], %2, 0x989680; "
                        "selp.b32 %0, 1, 0, p; }"
                        : "=r"(done) : "r"(mbar), "r"(ph) : "memory");
                } while (!done);
                ph ^= 1;
            }
            __syncthreads();

            // scores: 16 warps x 4 atoms
            float qreg[8];
            #pragma unroll
            for (int k = 0; k < 8; ++k) qreg[k] = qs[lane + 32 * k];
            #pragma unroll
            for (int aa = 0; aa < 4; ++aa) {
                int a = w * 4 + aa;
                const float* xr = xs + a * H;
                float p = 0.0f;
                #pragma unroll
                for (int k = 0; k < 8; ++k)
                    p = fmaf(xr[lane + 32 * k], qreg[k], p);
                #pragma unroll
                for (int off = 16; off; off >>= 1)
                    p += __shfl_xor_sync(0xffffffffu, p, off);
                if (lane == 0) sc[a] = p;
            }
            __syncthreads();

            // softmax over 64 (warp 0)
            if (w == 0) {
                float v0 = sc[lane], v1 = sc[lane + 32];
                float mx = fmaxf(v0, v1);
                #pragma unroll
                for (int off = 16; off; off >>= 1)
                    mx = fmaxf(mx, __shfl_xor_sync(0xffffffffu, mx, off));
                float e0 = __expf(v0 - mx), e1 = __expf(v1 - mx);
                float ssum = e0 + e1;
                #pragma unroll
                for (int off = 16; off; off >>= 1)
                    ssum += __shfl_xor_sync(0xffffffffu, ssum, off);
                float inv = 1.0f / ssum;
                sc[lane]      = e0 * inv;
                sc[lane + 32] = e1 * inv;
            }
            __syncthreads();

            // weighted sum: 512 threads, 2 halves of atoms
            {
                int j    = tid & (H - 1);
                int half = tid >> 8;
                const float* Xh = xs + half * 32 * H;
                float r = 0.0f;
                #pragma unroll
                for (int a0 = 0; a0 < 32; ++a0)
                    r = fmaf(sc[half * 32 + a0], Xh[a0 * H + j], r);
                red[tid] = r;
            }
            __syncthreads();   // xs fully consumed

            issue(jj + 1);     // refill buffer (overlaps reduce + gemm phase)

            if (tid < H) {
                float rr = red[tid] + red[tid + H];
                g_h[(size_t)b * H + tid] = rr;
                if (s == 2) out[(size_t)b * (2 * H) + H + tid] = rr;
            }
            __syncthreads();

            if (s < 2 && tid == 0) {
                __threadfence();
                atomicAdd(&g_flagR[s][b >> 7], 1);
            }
        }

        // ================= gemm phase s (gates for pass s+1) =================
        if (s < 2 && bid < 256) {
            int t  = bid;
            int m0 = (t >> 4) * 128;      // 128-row block  (== graph block t>>4)
            int n0 = (t & 15) * 64;       // 64-col tile

            if (tid == 0) {
                poll_eq(&g_flagR[s][t >> 4], 128);
                __threadfence();
            }
            __syncthreads();

            int mg = tid >> 4;            // 0..31 -> rows m0+4*mg..+3
            int ng = tid & 15;            // 0..15 -> cols n0+4*ng..+3
            int m  = m0 + mg * 4;

            unsigned long long acc[2][4];
            #pragma unroll
            for (int p = 0; p < 2; ++p)
                #pragma unroll
                for (int j = 0; j < 4; ++j) acc[p][j] = 0ull;

            for (int kh = 0; kh < 2; ++kh) {
                // stage Bs[n][k] (64 x 128, stride 136)
                #pragma unroll
                for (int j2 = 0; j2 < 4; ++j2) {
                    int id = tid + 512 * j2;
                    int n  = id >> 5;
                    int kq = id & 31;
                    float4 wv = *(const float4*)&g_Wc[(size_t)(n0 + n) * H + kh * 128 + kq * 4];
                    *(float4*)&Bs[n * BS_STRIDE + kq * 4] = wv;
                }
                __syncthreads();

                for (int kq = 0; kq < 32; ++kq) {
                    int k = kh * 128 + kq * 4;
                    float4 h0 = *(const float4*)&g_h[(size_t)(m + 0) * H + k];
                    float4 h1 = *(const float4*)&g_h[(size_t)(m + 1) * H + k];
                    float4 h2 = *(const float4*)&g_h[(size_t)(m + 2) * H + k];
                    float4 h3 = *(const float4*)&g_h[(size_t)(m + 3) * H + k];
                    unsigned long long a2[2][4];
                    a2[0][0] = pack2(h0.x, h1.x); a2[0][1] = pack2(h0.y, h1.y);
                    a2[0][2] = pack2(h0.z, h1.z); a2[0][3] = pack2(h0.w, h1.w);
                    a2[1][0] = pack2(h2.x, h3.x); a2[1][1] = pack2(h2.y, h3.y);
                    a2[1][2] = pack2(h2.z, h3.z); a2[1][3] = pack2(h2.w, h3.w);
                    #pragma unroll
                    for (int j = 0; j < 4; ++j) {
                        float4 bv = *(const float4*)&Bs[(ng * 4 + j) * BS_STRIDE + kq * 4];
                        unsigned long long bx = pack2(bv.x, bv.x), by = pack2(bv.y, bv.y);
                        unsigned long long bz = pack2(bv.z, bv.z), bw = pack2(bv.w, bv.w);
                        #pragma unroll
                        for (int p = 0; p < 2; ++p) {
                            ffma2(acc[p][j], a2[p][0], bx);
                            ffma2(acc[p][j], a2[p][1], by);
                            ffma2(acc[p][j], a2[p][2], bz);
                            ffma2(acc[p][j], a2[p][3], bw);
                        }
                    }
                }
                __syncthreads();   // Bs free for restage
            }

            // epilogue: 4 rows x 4 cols
            #pragma unroll
            for (int p = 0; p < 2; ++p) {
                float lo[4], hi[4];
                #pragma unroll
                for (int j = 0; j < 4; ++j) {
                    float2 cv = unpack2(acc[p][j]);
                    lo[j] = cv.x; hi[j] = cv.y;
                }
                int mr = m + 2 * p;
                *(float4*)&g_gates[(size_t)mr       * FOURH + n0 + ng * 4] =
                    make_float4(lo[0], lo[1], lo[2], lo[3]);
                *(float4*)&g_gates[(size_t)(mr + 1) * FOURH + n0 + ng * 4] =
                    make_float4(hi[0], hi[1], hi[2], hi[3]);
            }
            __syncthreads();
            if (tid == 0) {
                __threadfence();
                atomicAdd(&g_flagG[s][t >> 4], 1);
            }
        }
    }
}

// ---------------- launch ----------------
extern "C" void kernel_launch(void* const* d_in, const int* in_sizes, int n_in,
                              void* d_out, int out_size) {
    const float* x    = (const float*)d_in[0];
    const float* W_ih = (const float*)d_in[3];
    const float* W_hh = (const float*)d_in[4];
    const float* b_ih = (const float*)d_in[5];
    const float* b_hh = (const float*)d_in[6];
    float* out = (float*)d_out;

    cudaFuncSetAttribute(fused_kernel,
                         cudaFuncAttributeMaxDynamicSharedMemorySize,
                         (int)SM_BYTES);

    prep_kernel<<<1024, 256>>>(W_ih, W_hh, b_ih, b_hh);
    fused_kernel<<<GRID, 512, SM_BYTES>>>(x, out);
}

// round 12
// speedup vs baseline: 3.1445x; 3.1445x over previous
#include <cuda_runtime.h>
#include <cuda_fp16.h>
#include <cstdint>

#define H        256
#define FOURH    1024
#define NG       2048
#define APG      64
#define GRIDA    444          // attention: 3 CTAs per SM
#define TILE_F   (APG*H)
#define TILE_B   (TILE_F*4)   // fp32 tile bytes
#define TILE_HB  (TILE_F*2)   // fp16 tile bytes

// ---------------- device scratch ----------------
__device__ float   g_Wc[FOURH * H];
__device__ float   g_bc[FOURH];
__device__ float   g_q0[H];
__device__ float   g_c0[H];
__device__ float   g_c [NG * H];
__device__ float   g_h [NG * H];
__device__ float   g_gates[NG * FOURH];
__device__ __align__(128) __half2 g_xh2[(size_t)NG * 8192];   // fp16 copy of x

__device__ __forceinline__ float sigmoidf_(float v) {
    return 1.0f / (1.0f + __expf(-v));
}

// ---------------- prep ----------------
__global__ void prep_kernel(const float* __restrict__ W_ih,
                            const float* __restrict__ W_hh,
                            const float* __restrict__ b_ih,
                            const float* __restrict__ b_hh) {
    int idx = blockIdx.x * 256 + threadIdx.x;
    if (idx < FOURH * H) g_Wc[idx] = W_ih[idx] + W_hh[idx];
    if (idx < FOURH)     g_bc[idx] = b_ih[idx] + b_hh[idx];
    if (idx < H) {
        float gi = b_ih[idx]       + b_hh[idx];
        float gg = b_ih[512 + idx] + b_hh[512 + idx];
        float go = b_ih[768 + idx] + b_hh[768 + idx];
        float c  = sigmoidf_(gi) * tanhf(gg);
        g_c0[idx] = c;
        g_q0[idx] = sigmoidf_(go) * tanhf(c);
    }
}

// ---------------- packed f32x2 helpers ----------------
__device__ __forceinline__ unsigned long long pack2(float lo, float hi) {
    unsigned long long r;
    asm("mov.b64 %0, {%1, %2};" : "=l"(r) : "f"(lo), "f"(hi));
    return r;
}
__device__ __forceinline__ void ffma2(unsigned long long& d,
                                      unsigned long long a,
                                      unsigned long long b) {
    asm("fma.rn.f32x2 %0, %1, %2, %0;" : "+l"(d) : "l"(a), "l"(b));
}

// ---------------- GEMM: gates = h @ Wc^T (f32x2 FMA, R2-proven) ----------------
__global__ void __launch_bounds__(256) gemm_gates_kernel() {
    __shared__ float As[2][16][128];
    __shared__ float Bs[2][16][64];

    int tid = threadIdx.x;
    int tx  = tid & 15;
    int ty  = tid >> 4;
    int mb  = blockIdx.y * 128;
    int nb  = blockIdx.x * 64;

    int a_r0 = tid >> 2,  a_k = tid & 3;
    int a_r1 = (tid + 256) >> 2;
    int b_r  = tid >> 2,  b_k = tid & 3;

    unsigned long long acc[4][4];
    #pragma unroll
    for (int p = 0; p < 4; ++p)
        #pragma unroll
        for (int j = 0; j < 4; ++j) acc[p][j] = 0ull;

    float4 av0, av1, bv;
    av0 = *(const float4*)&g_h [(size_t)(mb + a_r0) * H + a_k * 4];
    av1 = *(const float4*)&g_h [(size_t)(mb + a_r1) * H + a_k * 4];
    bv  = *(const float4*)&g_Wc[(size_t)(nb + b_r ) * H + b_k * 4];
    {
        As[0][a_k*4+0][a_r0] = av0.x; As[0][a_k*4+1][a_r0] = av0.y;
        As[0][a_k*4+2][a_r0] = av0.z; As[0][a_k*4+3][a_r0] = av0.w;
        As[0][a_k*4+0][a_r1] = av1.x; As[0][a_k*4+1][a_r1] = av1.y;
        As[0][a_k*4+2][a_r1] = av1.z; As[0][a_k*4+3][a_r1] = av1.w;
        Bs[0][b_k*4+0][b_r]  = bv.x;  Bs[0][b_k*4+1][b_r]  = bv.y;
        Bs[0][b_k*4+2][b_r]  = bv.z;  Bs[0][b_k*4+3][b_r]  = bv.w;
    }
    __syncthreads();

    const int NS = H / 16;
    for (int s = 0; s < NS; ++s) {
        int buf = s & 1;
        if (s + 1 < NS) {
            int kk = (s + 1) * 16;
            av0 = *(const float4*)&g_h [(size_t)(mb + a_r0) * H + kk + a_k * 4];
            av1 = *(const float4*)&g_h [(size_t)(mb + a_r1) * H + kk + a_k * 4];
            bv  = *(const float4*)&g_Wc[(size_t)(nb + b_r ) * H + kk + b_k * 4];
        }
        #pragma unroll
        for (int k = 0; k < 16; ++k) {
            unsigned long long a2[4];
            #pragma unroll
            for (int p = 0; p < 4; ++p)
                a2[p] = *(const unsigned long long*)&As[buf][k][ty * 8 + 2 * p];
            float4 b4 = *(const float4*)&Bs[buf][k][tx * 4];
            unsigned long long b2[4];
            b2[0] = pack2(b4.x, b4.x); b2[1] = pack2(b4.y, b4.y);
            b2[2] = pack2(b4.z, b4.z); b2[3] = pack2(b4.w, b4.w);
            #pragma unroll
            for (int p = 0; p < 4; ++p)
                #pragma unroll
                for (int j = 0; j < 4; ++j)
                    ffma2(acc[p][j], a2[p], b2[j]);
        }
        if (s + 1 < NS) {
            int nbuf = 1 - buf;
            As[nbuf][a_k*4+0][a_r0] = av0.x; As[nbuf][a_k*4+1][a_r0] = av0.y;
            As[nbuf][a_k*4+2][a_r0] = av0.z; As[nbuf][a_k*4+3][a_r0] = av0.w;
            As[nbuf][a_k*4+0][a_r1] = av1.x; As[nbuf][a_k*4+1][a_r1] = av1.y;
            As[nbuf][a_k*4+2][a_r1] = av1.z; As[nbuf][a_k*4+3][a_r1] = av1.w;
            Bs[nbuf][b_k*4+0][b_r]  = bv.x;  Bs[nbuf][b_k*4+1][b_r]  = bv.y;
            Bs[nbuf][b_k*4+2][b_r]  = bv.z;  Bs[nbuf][b_k*4+3][b_r]  = bv.w;
        }
        __syncthreads();
    }

    #pragma unroll
    for (int p = 0; p < 4; ++p) {
        float lo[4], hi[4];
        #pragma unroll
        for (int j = 0; j < 4; ++j) {
            union { unsigned long long u; float2 f; } cv;
            cv.u = acc[p][j];
            lo[j] = cv.f.x; hi[j] = cv.f.y;
        }
        int m0 = mb + ty * 8 + 2 * p;
        *(float4*)&g_gates[(size_t)m0       * FOURH + nb + tx * 4] =
            make_float4(lo[0], lo[1], lo[2], lo[3]);
        *(float4*)&g_gates[(size_t)(m0 + 1) * FOURH + nb + tx * 4] =
            make_float4(hi[0], hi[1], hi[2], hi[3]);
    }
}

// ---------------- pass 0: fp32 attention (q = q0) + fp16 tile export ----------------
#define A32_FLOATS (TILE_F + H + APG + 512)
#define A32_SMEM   (A32_FLOATS*4 + 8)

__global__ void __launch_bounds__(512, 3) attn0_kernel(const float* __restrict__ x) {
    extern __shared__ __align__(16) unsigned char smraw[];
    float* xs  = (float*)smraw;              // [64][256] fp32
    float* qs  = xs + TILE_F;                // [256]
    float* sc  = qs + H;                     // [64]
    float* red = sc + APG;                   // [512]
    uint32_t smem_base;
    asm("{ .reg .u64 t; cvta.to.shared.u64 t, %1; cvt.u32.u64 %0, t; }"
        : "=r"(smem_base) : "l"(smraw));
    uint32_t mbar = smem_base + A32_FLOATS * 4;

    int tid  = threadIdx.x;
    int lane = tid & 31;
    int w    = tid >> 5;

    if (tid == 0)
        asm volatile("mbarrier.init.shared.b64 [%0], 1;" :: "r"(mbar) : "memory");
    __syncthreads();

    int ph = 0;
    for (int b = blockIdx.x; b < NG; b += GRIDA) {
        if (tid == 0) {
            asm volatile("mbarrier.arrive.expect_tx.shared.b64 _, [%0], %1;"
                         :: "r"(mbar), "r"(TILE_B) : "memory");
            asm volatile("cp.async.bulk.shared::cta.global.mbarrier::complete_tx::bytes "
                         "[%0], [%1], %2, [%3];"
                         :: "r"(smem_base), "l"(x + (size_t)b * TILE_F),
                            "r"(TILE_B), "r"(mbar) : "memory");
        }
        if (tid < H) qs[tid] = g_q0[tid];

        {
            uint32_t done;
            do {
                asm volatile(
                    "{ .reg .pred p; "
                    "mbarrier.try_wait.parity.acquire.cta.shared::cta.b64 p, [%1], %2, 0x989680; "
                    "selp.b32 %0, 1, 0, p; }"
                    : "=r"(done) : "r"(mbar), "r"(ph) : "memory");
            } while (!done);
            ph ^= 1;
        }
        __syncthreads();

        // export tile as fp16 (L2-resident copy for passes 1-2)
        {
            const float4* src4 = (const float4*)xs;
            uint2* dst2 = (uint2*)(g_xh2 + (size_t)b * 8192);
            #pragma unroll
            for (int it = 0; it < 8; ++it) {
                int idx = tid + it * 512;
                float4 v = src4[idx];
                __half2 h0 = __floats2half2_rn(v.x, v.y);
                __half2 h1 = __floats2half2_rn(v.z, v.w);
                uint2 u;
                u.x = *(uint32_t*)&h0;
                u.y = *(uint32_t*)&h1;
                dst2[idx] = u;
            }
        }

        // scores: 16 warps x 4 atoms
        float qreg[8];
        #pragma unroll
        for (int k = 0; k < 8; ++k) qreg[k] = qs[lane + 32 * k];
        #pragma unroll
        for (int aa = 0; aa < 4; ++aa) {
            int a = w * 4 + aa;
            const float* xr = xs + a * H;
            float p = 0.0f;
            #pragma unroll
            for (int k = 0; k < 8; ++k)
                p = fmaf(xr[lane + 32 * k], qreg[k], p);
            #pragma unroll
            for (int off = 16; off; off >>= 1)
                p += __shfl_xor_sync(0xffffffffu, p, off);
            if (lane == 0) sc[a] = p;
        }
        __syncthreads();

        // softmax over 64 (warp 0)
        if (w == 0) {
            float v0 = sc[lane], v1 = sc[lane + 32];
            float mx = fmaxf(v0, v1);
            #pragma unroll
            for (int off = 16; off; off >>= 1)
                mx = fmaxf(mx, __shfl_xor_sync(0xffffffffu, mx, off));
            float e0 = __expf(v0 - mx), e1 = __expf(v1 - mx);
            float s = e0 + e1;
            #pragma unroll
            for (int off = 16; off; off >>= 1)
                s += __shfl_xor_sync(0xffffffffu, s, off);
            float inv = 1.0f / s;
            sc[lane]      = e0 * inv;
            sc[lane + 32] = e1 * inv;
        }
        __syncthreads();

        // weighted sum
        {
            int j    = tid & (H - 1);
            int half = tid >> 8;
            const float* Xh = xs + half * 32 * H;
            float r = 0.0f;
            #pragma unroll
            for (int a0 = 0; a0 < 32; ++a0)
                r = fmaf(sc[half * 32 + a0], Xh[a0 * H + j], r);
            red[tid] = r;
        }
        __syncthreads();
        if (tid < H)
            g_h[(size_t)b * H + tid] = red[tid] + red[tid + H];
        __syncthreads();
    }
}

// ---------------- passes 1-2: fp16 attention (x from L2) ----------------
// SMEM: xs_h [64][128] half2 (32KB) | qs[256] | sc[64] | red[512] float2
#define A16_BYTES  (TILE_HB + (H + APG + 1024)*4 + 8)

__global__ void __launch_bounds__(512, 3) attnh_kernel(float* __restrict__ out,
                                                       int mode) {
    extern __shared__ __align__(16) unsigned char smraw[];
    __half2* xsh = (__half2*)smraw;                    // [64][128]
    float* qs  = (float*)(smraw + TILE_HB);            // [256]
    float* sc  = qs + H;                               // [64]
    float* red = sc + APG;                             // [512] float2
    uint32_t smem_base;
    asm("{ .reg .u64 t; cvta.to.shared.u64 t, %1; cvt.u32.u64 %0, t; }"
        : "=r"(smem_base) : "l"(smraw));
    uint32_t mbar = smem_base + (uint32_t)(TILE_HB + (H + APG + 1024) * 4);

    int tid  = threadIdx.x;
    int lane = tid & 31;
    int w    = tid >> 5;

    if (tid == 0)
        asm volatile("mbarrier.init.shared.b64 [%0], 1;" :: "r"(mbar) : "memory");
    __syncthreads();

    int ph = 0;
    for (int b = blockIdx.x; b < NG; b += GRIDA) {
        if (tid == 0) {
            asm volatile("mbarrier.arrive.expect_tx.shared.b64 _, [%0], %1;"
                         :: "r"(mbar), "r"(TILE_HB) : "memory");
            asm volatile("cp.async.bulk.shared::cta.global.mbarrier::complete_tx::bytes "
                         "[%0], [%1], %2, [%3];"
                         :: "r"(smem_base), "l"(g_xh2 + (size_t)b * 8192),
                            "r"(TILE_HB), "r"(mbar) : "memory");
        }

        // fused LSTM pointwise -> q (overlaps TMA)
        if (tid < H) {
            int j = tid;
            const float* gr = g_gates + (size_t)b * FOURH;
            float gi = gr[j]       + g_bc[j];
            float gf = gr[256 + j] + g_bc[256 + j];
            float gg = gr[512 + j] + g_bc[512 + j];
            float go = gr[768 + j] + g_bc[768 + j];
            float cp = (mode == 1) ? g_c0[j] : g_c[(size_t)b * H + j];
            float c  = sigmoidf_(gf) * cp + sigmoidf_(gi) * tanhf(gg);
            float q  = sigmoidf_(go) * tanhf(c);
            if (mode == 1) g_c[(size_t)b * H + j] = c;
            if (mode == 2) out[(size_t)b * (2 * H) + j] = q;
            qs[j] = q;
        }

        {
            uint32_t done;
            do {
                asm volatile(
                    "{ .reg .pred p; "
                    "mbarrier.try_wait.parity.acquire.cta.shared::cta.b64 p, [%1], %2, 0x989680; "
                    "selp.b32 %0, 1, 0, p; }"
                    : "=r"(done) : "r"(mbar), "r"(ph) : "memory");
            } while (!done);
            ph ^= 1;
        }
        __syncthreads();

        // scores: 16 warps x 4 atoms; fp16 x, fp32 accumulate
        float2 q0 = *(const float2*)&qs[2 * lane];
        float2 q1 = *(const float2*)&qs[64 + 2 * lane];
        float2 q2 = *(const float2*)&qs[128 + 2 * lane];
        float2 q3 = *(const float2*)&qs[192 + 2 * lane];
        #pragma unroll
        for (int aa = 0; aa < 4; ++aa) {
            int a = w * 4 + aa;
            const __half2* row = xsh + a * 128;
            float2 x0 = __half22float2(row[lane]);
            float2 x1 = __half22float2(row[32 + lane]);
            float2 x2 = __half22float2(row[64 + lane]);
            float2 x3 = __half22float2(row[96 + lane]);
            float p = x0.x*q0.x + x0.y*q0.y + x1.x*q1.x + x1.y*q1.y
                    + x2.x*q2.x + x2.y*q2.y + x3.x*q3.x + x3.y*q3.y;
            #pragma unroll
            for (int off = 16; off; off >>= 1)
                p += __shfl_xor_sync(0xffffffffu, p, off);
            if (lane == 0) sc[a] = p;
        }
        __syncthreads();

        // softmax over 64 (warp 0)
        if (w == 0) {
            float v0 = sc[lane], v1 = sc[lane + 32];
            float mx = fmaxf(v0, v1);
            #pragma unroll
            for (int off = 16; off; off >>= 1)
                mx = fmaxf(mx, __shfl_xor_sync(0xffffffffu, mx, off));
            float e0 = __expf(v0 - mx), e1 = __expf(v1 - mx);
            float s = e0 + e1;
            #pragma unroll
            for (int off = 16; off; off >>= 1)
                s += __shfl_xor_sync(0xffffffffu, s, off);
            float inv = 1.0f / s;
            sc[lane]      = e0 * inv;
            sc[lane + 32] = e1 * inv;
        }
        __syncthreads();

        // weighted sum: thread -> feature pair (2fp, 2fp+1), quarter of atoms
        {
            int fp = tid & 127;
            int qt = tid >> 7;
            float2 r2 = make_float2(0.0f, 0.0f);
            const __half2* Xq = xsh + qt * 16 * 128 + fp;
            #pragma unroll
            for (int a = 0; a < 16; ++a) {
                float sw = sc[qt * 16 + a];
                float2 xv = __half22float2(Xq[a * 128]);
                r2.x = fmaf(sw, xv.x, r2.x);
                r2.y = fmaf(sw, xv.y, r2.y);
            }
            *(float2*)&red[tid * 2] = r2;
        }
        __syncthreads();
        if (tid < 128) {
            float2 r0 = *(const float2*)&red[tid * 2];
            float2 r1 = *(const float2*)&red[(tid + 128) * 2];
            float2 r2 = *(const float2*)&red[(tid + 256) * 2];
            float2 r3 = *(const float2*)&red[(tid + 384) * 2];
            float2 rr = make_float2(r0.x + r1.x + r2.x + r3.x,
                                    r0.y + r1.y + r2.y + r3.y);
            *(float2*)&g_h[(size_t)b * H + 2 * tid] = rr;
            if (mode == 2)
                *(float2*)&out[(size_t)b * (2 * H) + H + 2 * tid] = rr;
        }
        __syncthreads();
    }
}

// ---------------- launch ----------------
extern "C" void kernel_launch(void* const* d_in, const int* in_sizes, int n_in,
                              void* d_out, int out_size) {
    const float* x    = (const float*)d_in[0];
    const float* W_ih = (const float*)d_in[3];
    const float* W_hh = (const float*)d_in[4];
    const float* b_ih = (const float*)d_in[5];
    const float* b_hh = (const float*)d_in[6];
    float* out = (float*)d_out;

    cudaFuncSetAttribute(attn0_kernel,
                         cudaFuncAttributeMaxDynamicSharedMemorySize, (int)A32_SMEM);
    cudaFuncSetAttribute(attnh_kernel,
                         cudaFuncAttributeMaxDynamicSharedMemorySize, (int)A16_BYTES);

    prep_kernel<<<1024, 256>>>(W_ih, W_hh, b_ih, b_hh);

    dim3 ggrid(FOURH / 64, NG / 128);

    attn0_kernel<<<GRIDA, 512, A32_SMEM>>>(x);                 // step 0 + fp16 export
    gemm_gates_kernel<<<ggrid, 256>>>();
    attnh_kernel<<<GRIDA, 512, A16_BYTES>>>(nullptr, 1);       // step 1 (L2 x)
    gemm_gates_kernel<<<ggrid, 256>>>();
    attnh_kernel<<<GRIDA, 512, A16_BYTES>>>(out, 2);           // step 2 (L2 x)
}

// round 13
// speedup vs baseline: 3.7533x; 1.1936x over previous
#include <cuda_runtime.h>
#include <cuda_fp16.h>
#include <mma.h>
#include <cstdint>

using namespace nvcuda;

#define H        256
#define FOURH    1024
#define NG       2048
#define APG      64
#define GRIDA    444          // attention: 3 CTAs per SM
#define TILE_F   (APG*H)
#define TILE_B   (TILE_F*4)   // fp32 tile bytes
#define TILE_HB  (TILE_F*2)   // fp16 tile bytes

// ---------------- device scratch ----------------
__device__ float   g_Wc[FOURH * H];                      // unused by gemm now (kept for prep simplicity)
__device__ __align__(128) __half g_Wc16[FOURH * H];      // fp16 folded weights
__device__ float   g_bc[FOURH];
__device__ float   g_q0[H];
__device__ float   g_c0[H];
__device__ float   g_c [NG * H];
__device__ __align__(128) __half g_h16[NG * H];          // fp16 h (= r)
__device__ float   g_gates[NG * FOURH];
__device__ __align__(128) __half2 g_xh2[(size_t)NG * 8192];  // fp16 copy of x

__device__ __forceinline__ float sigmoidf_(float v) {
    return 1.0f / (1.0f + __expf(-v));
}

// ---------------- prep ----------------
__global__ void prep_kernel(const float* __restrict__ W_ih,
                            const float* __restrict__ W_hh,
                            const float* __restrict__ b_ih,
                            const float* __restrict__ b_hh) {
    int idx = blockIdx.x * 256 + threadIdx.x;
    if (idx < FOURH * H) {
        float wc = W_ih[idx] + W_hh[idx];
        g_Wc[idx]   = wc;
        g_Wc16[idx] = __float2half(wc);
    }
    if (idx < FOURH) g_bc[idx] = b_ih[idx] + b_hh[idx];
    if (idx < H) {
        float gi = b_ih[idx]       + b_hh[idx];
        float gg = b_ih[512 + idx] + b_hh[512 + idx];
        float go = b_ih[768 + idx] + b_hh[768 + idx];
        float c  = sigmoidf_(gi) * tanhf(gg);
        g_c0[idx] = c;
        g_q0[idx] = sigmoidf_(go) * tanhf(c);
    }
}

// ---------------- GEMM: gates = h16 @ Wc16^T via wmma (fp32 accum) ----------------
// CTA tile 128m x 128n, K=256 fully staged in SMEM (128KB). 8 warps a 32x64.
#define GW_SMEM (2 * 128 * 256 * 2)   // A block + B block, fp16

__global__ void __launch_bounds__(256) gemm_wmma_kernel() {
    extern __shared__ __align__(16) __half smh[];
    __half* As = smh;                  // [128][256]
    __half* Bs = smh + 128 * 256;      // [128][256]  (rows = n, cols = k)

    int tid = threadIdx.x;
    int mb  = blockIdx.y * 128;
    int nb  = blockIdx.x * 128;

    // stage A and B blocks (4096 uint4 each, 16 per thread)
    {
        const uint4* srcA = (const uint4*)(g_h16  + (size_t)mb * H);
        const uint4* srcB = (const uint4*)(g_Wc16 + (size_t)nb * H);
        uint4* dA = (uint4*)As;
        uint4* dB = (uint4*)Bs;
        #pragma unroll
        for (int i = 0; i < 16; ++i) dA[tid + i * 256] = srcA[tid + i * 256];
        #pragma unroll
        for (int i = 0; i < 16; ++i) dB[tid + i * 256] = srcB[tid + i * 256];
    }
    __syncthreads();

    int w  = tid >> 5;
    int wm = (w >> 1) * 32;     // 0,32,64,96
    int wn = (w & 1) * 64;      // 0,64

    wmma::fragment<wmma::accumulator, 16, 16, 16, float> acc[2][4];
    #pragma unroll
    for (int i = 0; i < 2; ++i)
        #pragma unroll
        for (int j = 0; j < 4; ++j) wmma::fill_fragment(acc[i][j], 0.0f);

    #pragma unroll
    for (int k = 0; k < H; k += 16) {
        wmma::fragment<wmma::matrix_a, 16, 16, 16, __half, wmma::row_major> af[2];
        wmma::fragment<wmma::matrix_b, 16, 16, 16, __half, wmma::col_major> bf[4];
        #pragma unroll
        for (int i = 0; i < 2; ++i)
            wmma::load_matrix_sync(af[i], As + (wm + 16 * i) * H + k, H);
        #pragma unroll
        for (int j = 0; j < 4; ++j)
            wmma::load_matrix_sync(bf[j], Bs + (wn + 16 * j) * H + k, H);
        #pragma unroll
        for (int i = 0; i < 2; ++i)
            #pragma unroll
            for (int j = 0; j < 4; ++j)
                wmma::mma_sync(acc[i][j], af[i], bf[j], acc[i][j]);
    }

    #pragma unroll
    for (int i = 0; i < 2; ++i)
        #pragma unroll
        for (int j = 0; j < 4; ++j)
            wmma::store_matrix_sync(
                &g_gates[(size_t)(mb + wm + 16 * i) * FOURH + nb + wn + 16 * j],
                acc[i][j], FOURH, wmma::mem_row_major);
}

// ---------------- pass 0: fp32 attention (q = q0) + fp16 tile export ----------------
#define A32_FLOATS (TILE_F + H + APG + 512)
#define A32_SMEM   (A32_FLOATS*4 + 8)

__global__ void __launch_bounds__(512, 3) attn0_kernel(const float* __restrict__ x) {
    extern __shared__ __align__(16) unsigned char smraw[];
    float* xs  = (float*)smraw;              // [64][256] fp32
    float* qs  = xs + TILE_F;                // [256]
    float* sc  = qs + H;                     // [64]
    float* red = sc + APG;                   // [512]
    uint32_t smem_base;
    asm("{ .reg .u64 t; cvta.to.shared.u64 t, %1; cvt.u32.u64 %0, t; }"
        : "=r"(smem_base) : "l"(smraw));
    uint32_t mbar = smem_base + A32_FLOATS * 4;

    int tid  = threadIdx.x;
    int lane = tid & 31;
    int w    = tid >> 5;

    if (tid == 0)
        asm volatile("mbarrier.init.shared.b64 [%0], 1;" :: "r"(mbar) : "memory");
    __syncthreads();

    int ph = 0;
    for (int b = blockIdx.x; b < NG; b += GRIDA) {
        if (tid == 0) {
            asm volatile("mbarrier.arrive.expect_tx.shared.b64 _, [%0], %1;"
                         :: "r"(mbar), "r"(TILE_B) : "memory");
            asm volatile("cp.async.bulk.shared::cta.global.mbarrier::complete_tx::bytes "
                         "[%0], [%1], %2, [%3];"
                         :: "r"(smem_base), "l"(x + (size_t)b * TILE_F),
                            "r"(TILE_B), "r"(mbar) : "memory");
        }
        if (tid < H) qs[tid] = g_q0[tid];

        {
            uint32_t done;
            do {
                asm volatile(
                    "{ .reg .pred p; "
                    "mbarrier.try_wait.parity.acquire.cta.shared::cta.b64 p, [%1], %2, 0x989680; "
                    "selp.b32 %0, 1, 0, p; }"
                    : "=r"(done) : "r"(mbar), "r"(ph) : "memory");
            } while (!done);
            ph ^= 1;
        }
        __syncthreads();

        // export tile as fp16 (L2-resident copy for passes 1-2)
        {
            const float4* src4 = (const float4*)xs;
            uint2* dst2 = (uint2*)(g_xh2 + (size_t)b * 8192);
            #pragma unroll
            for (int it = 0; it < 8; ++it) {
                int idx = tid + it * 512;
                float4 v = src4[idx];
                __half2 h0 = __floats2half2_rn(v.x, v.y);
                __half2 h1 = __floats2half2_rn(v.z, v.w);
                uint2 u;
                u.x = *(uint32_t*)&h0;
                u.y = *(uint32_t*)&h1;
                dst2[idx] = u;
            }
        }

        // scores: 16 warps x 4 atoms
        float qreg[8];
        #pragma unroll
        for (int k = 0; k < 8; ++k) qreg[k] = qs[lane + 32 * k];
        #pragma unroll
        for (int aa = 0; aa < 4; ++aa) {
            int a = w * 4 + aa;
            const float* xr = xs + a * H;
            float p = 0.0f;
            #pragma unroll
            for (int k = 0; k < 8; ++k)
                p = fmaf(xr[lane + 32 * k], qreg[k], p);
            #pragma unroll
            for (int off = 16; off; off >>= 1)
                p += __shfl_xor_sync(0xffffffffu, p, off);
            if (lane == 0) sc[a] = p;
        }
        __syncthreads();

        // softmax over 64 (warp 0)
        if (w == 0) {
            float v0 = sc[lane], v1 = sc[lane + 32];
            float mx = fmaxf(v0, v1);
            #pragma unroll
            for (int off = 16; off; off >>= 1)
                mx = fmaxf(mx, __shfl_xor_sync(0xffffffffu, mx, off));
            float e0 = __expf(v0 - mx), e1 = __expf(v1 - mx);
            float s = e0 + e1;
            #pragma unroll
            for (int off = 16; off; off >>= 1)
                s += __shfl_xor_sync(0xffffffffu, s, off);
            float inv = 1.0f / s;
            sc[lane]      = e0 * inv;
            sc[lane + 32] = e1 * inv;
        }
        __syncthreads();

        // weighted sum
        {
            int j    = tid & (H - 1);
            int half = tid >> 8;
            const float* Xh = xs + half * 32 * H;
            float r = 0.0f;
            #pragma unroll
            for (int a0 = 0; a0 < 32; ++a0)
                r = fmaf(sc[half * 32 + a0], Xh[a0 * H + j], r);
            red[tid] = r;
        }
        __syncthreads();
        if (tid < H)
            g_h16[(size_t)b * H + tid] = __float2half(red[tid] + red[tid + H]);
        __syncthreads();
    }
}

// ---------------- passes 1-2: fp16 attention (x from L2) ----------------
#define A16_BYTES  (TILE_HB + (H + APG + 1024)*4 + 8)

__global__ void __launch_bounds__(512, 3) attnh_kernel(float* __restrict__ out,
                                                       int mode) {
    extern __shared__ __align__(16) unsigned char smraw[];
    __half2* xsh = (__half2*)smraw;                    // [64][128]
    float* qs  = (float*)(smraw + TILE_HB);            // [256]
    float* sc  = qs + H;                               // [64]
    float* red = sc + APG;                             // [512] float2
    uint32_t smem_base;
    asm("{ .reg .u64 t; cvta.to.shared.u64 t, %1; cvt.u32.u64 %0, t; }"
        : "=r"(smem_base) : "l"(smraw));
    uint32_t mbar = smem_base + (uint32_t)(TILE_HB + (H + APG + 1024) * 4);

    int tid  = threadIdx.x;
    int lane = tid & 31;
    int w    = tid >> 5;

    if (tid == 0)
        asm volatile("mbarrier.init.shared.b64 [%0], 1;" :: "r"(mbar) : "memory");
    __syncthreads();

    int ph = 0;
    for (int b = blockIdx.x; b < NG; b += GRIDA) {
        if (tid == 0) {
            asm volatile("mbarrier.arrive.expect_tx.shared.b64 _, [%0], %1;"
                         :: "r"(mbar), "r"(TILE_HB) : "memory");
            asm volatile("cp.async.bulk.shared::cta.global.mbarrier::complete_tx::bytes "
                         "[%0], [%1], %2, [%3];"
                         :: "r"(smem_base), "l"(g_xh2 + (size_t)b * 8192),
                            "r"(TILE_HB), "r"(mbar) : "memory");
        }

        // fused LSTM pointwise -> q (overlaps TMA)
        if (tid < H) {
            int j = tid;
            const float* gr = g_gates + (size_t)b * FOURH;
            float gi = gr[j]       + g_bc[j];
            float gf = gr[256 + j] + g_bc[256 + j];
            float gg = gr[512 + j] + g_bc[512 + j];
            float go = gr[768 + j] + g_bc[768 + j];
            float cp = (mode == 1) ? g_c0[j] : g_c[(size_t)b * H + j];
            float c  = sigmoidf_(gf) * cp + sigmoidf_(gi) * tanhf(gg);
            float q  = sigmoidf_(go) * tanhf(c);
            if (mode == 1) g_c[(size_t)b * H + j] = c;
            if (mode == 2) out[(size_t)b * (2 * H) + j] = q;
            qs[j] = q;
        }

        {
            uint32_t done;
            do {
                asm volatile(
                    "{ .reg .pred p; "
                    "mbarrier.try_wait.parity.acquire.cta.shared::cta.b64 p, [%1], %2, 0x989680; "
                    "selp.b32 %0, 1, 0, p; }"
                    : "=r"(done) : "r"(mbar), "r"(ph) : "memory");
            } while (!done);
            ph ^= 1;
        }
        __syncthreads();

        // scores: 16 warps x 4 atoms; fp16 x, fp32 accumulate
        float2 q0 = *(const float2*)&qs[2 * lane];
        float2 q1 = *(const float2*)&qs[64 + 2 * lane];
        float2 q2 = *(const float2*)&qs[128 + 2 * lane];
        float2 q3 = *(const float2*)&qs[192 + 2 * lane];
        #pragma unroll
        for (int aa = 0; aa < 4; ++aa) {
            int a = w * 4 + aa;
            const __half2* row = xsh + a * 128;
            float2 x0 = __half22float2(row[lane]);
            float2 x1 = __half22float2(row[32 + lane]);
            float2 x2 = __half22float2(row[64 + lane]);
            float2 x3 = __half22float2(row[96 + lane]);
            float p = x0.x*q0.x + x0.y*q0.y + x1.x*q1.x + x1.y*q1.y
                    + x2.x*q2.x + x2.y*q2.y + x3.x*q3.x + x3.y*q3.y;
            #pragma unroll
            for (int off = 16; off; off >>= 1)
                p += __shfl_xor_sync(0xffffffffu, p, off);
            if (lane == 0) sc[a] = p;
        }
        __syncthreads();

        // softmax over 64 (warp 0)
        if (w == 0) {
            float v0 = sc[lane], v1 = sc[lane + 32];
            float mx = fmaxf(v0, v1);
            #pragma unroll
            for (int off = 16; off; off >>= 1)
                mx = fmaxf(mx, __shfl_xor_sync(0xffffffffu, mx, off));
            float e0 = __expf(v0 - mx), e1 = __expf(v1 - mx);
            float s = e0 + e1;
            #pragma unroll
            for (int off = 16; off; off >>= 1)
                s += __shfl_xor_sync(0xffffffffu, s, off);
            float inv = 1.0f / s;
            sc[lane]      = e0 * inv;
            sc[lane + 32] = e1 * inv;
        }
        __syncthreads();

        // weighted sum: thread -> feature pair, quarter of atoms
        {
            int fp = tid & 127;
            int qt = tid >> 7;
            float2 r2 = make_float2(0.0f, 0.0f);
            const __half2* Xq = xsh + qt * 16 * 128 + fp;
            #pragma unroll
            for (int a = 0; a < 16; ++a) {
                float sw = sc[qt * 16 + a];
                float2 xv = __half22float2(Xq[a * 128]);
                r2.x = fmaf(sw, xv.x, r2.x);
                r2.y = fmaf(sw, xv.y, r2.y);
            }
            *(float2*)&red[tid * 2] = r2;
        }
        __syncthreads();
        if (tid < 128) {
            float2 r0 = *(const float2*)&red[tid * 2];
            float2 r1 = *(const float2*)&red[(tid + 128) * 2];
            float2 r2 = *(const float2*)&red[(tid + 256) * 2];
            float2 r3 = *(const float2*)&red[(tid + 384) * 2];
            float2 rr = make_float2(r0.x + r1.x + r2.x + r3.x,
                                    r0.y + r1.y + r2.y + r3.y);
            ((__half2*)g_h16)[(size_t)b * 128 + tid] = __floats2half2_rn(rr.x, rr.y);
            if (mode == 2)
                *(float2*)&out[(size_t)b * (2 * H) + H + 2 * tid] = rr;
        }
        __syncthreads();
    }
}

// ---------------- launch ----------------
extern "C" void kernel_launch(void* const* d_in, const int* in_sizes, int n_in,
                              void* d_out, int out_size) {
    const float* x    = (const float*)d_in[0];
    const float* W_ih = (const float*)d_in[3];
    const float* W_hh = (const float*)d_in[4];
    const float* b_ih = (const float*)d_in[5];
    const float* b_hh = (const float*)d_in[6];
    float* out = (float*)d_out;

    cudaFuncSetAttribute(attn0_kernel,
                         cudaFuncAttributeMaxDynamicSharedMemorySize, (int)A32_SMEM);
    cudaFuncSetAttribute(attnh_kernel,
                         cudaFuncAttributeMaxDynamicSharedMemorySize, (int)A16_BYTES);
    cudaFuncSetAttribute(gemm_wmma_kernel,
                         cudaFuncAttributeMaxDynamicSharedMemorySize, (int)GW_SMEM);

    prep_kernel<<<1024, 256>>>(W_ih, W_hh, b_ih, b_hh);

    dim3 ggrid(FOURH / 128, NG / 128);

    attn0_kernel<<<GRIDA, 512, A32_SMEM>>>(x);                 // step 0 + fp16 export
    gemm_wmma_kernel<<<ggrid, 256, GW_SMEM>>>();
    attnh_kernel<<<GRIDA, 512, A16_BYTES>>>(nullptr, 1);       // step 1 (L2 x)
    gemm_wmma_kernel<<<ggrid, 256, GW_SMEM>>>();
    attnh_kernel<<<GRIDA, 512, A16_BYTES>>>(out, 2);           // step 2 (L2 x)
}